// round 2
// baseline (speedup 1.0000x reference)
#include <cuda_runtime.h>

// FlexHNN fused kernel, fp32 SIMT baseline.
// Pipeline per 64-row tile (all in one kernel, one block per tile):
//   t1 = tanh(z @ hW1^T + hb1)                      -> sA
//   a2 = t1 @ hW2^T + hb2 ; s2 = 1 - tanh(a2)^2     (register epilogue)
//   f  = z @ fW1^T + fb1 ; g = .5*f*s2 + .5*tanh(f) -> sA
//   f2 = g @ fW2^T + fb2 ; s1 recomputed from z     (register epilogue)
//   h  = .5*f2*s1 + .5*tanh(f2)                     -> sA
//   o  = h @ fW3^T + fb3 ; dz = [o[:,8:], -o[:,:8]] -> out

#define DZv 16
#define Hv 256
#define BM 64
#define NTHREADS 256
#define KC 32
#define NC (Hv / KC)      // 8 K-chunks
#define WKS 33            // weight tile row stride (floats), bank-conflict-free
#define AS (Hv + 1)       // 257: activation row stride
#define ZS (DZv + 1)      // 17:  z / W1 row stride

__device__ __forceinline__ float fast_tanh(float x) {
    // tanh(x) = 1 - 2/(exp(2x)+1); safe at +-inf, ~1e-7 rel error via __expf
    float e = __expf(2.0f * x);
    return 1.0f - 2.0f / (e + 1.0f);
}

// acc[r][c] = sum_k sA[row0+r][k] * Wg[lane+32c][k]   (Wg row-major [256][256])
__device__ __forceinline__ void big_gemm(const float* __restrict__ Wg,
                                         const float* __restrict__ sA,
                                         float* __restrict__ sW,
                                         int tid, int lane, int row0,
                                         float (&acc)[8][8])
{
#pragma unroll
    for (int r = 0; r < 8; ++r)
#pragma unroll
        for (int c = 0; c < 8; ++c) acc[r][c] = 0.0f;

    float4 ld[8];
    // prefetch chunk 0: 256 rows x 32 k = 2048 float4, 8 per thread
#pragma unroll
    for (int i = 0; i < 8; ++i) {
        int idx = i * NTHREADS + tid;
        int j = idx >> 3, q = idx & 7;
        ld[i] = *(const float4*)(Wg + j * Hv + q * 4);
    }

    for (int ch = 0; ch < NC; ++ch) {
        // stage current chunk into sW[j*33 + k] (stores conflict-free: bank = j+4q+s)
#pragma unroll
        for (int i = 0; i < 8; ++i) {
            int idx = i * NTHREADS + tid;
            int j = idx >> 3, q = idx & 7;
            float* p = sW + j * WKS + q * 4;
            p[0] = ld[i].x; p[1] = ld[i].y; p[2] = ld[i].z; p[3] = ld[i].w;
        }
        __syncthreads();

        // prefetch next chunk (LDG latency hidden behind compute)
        if (ch + 1 < NC) {
            int k0n = (ch + 1) * KC;
#pragma unroll
            for (int i = 0; i < 8; ++i) {
                int idx = i * NTHREADS + tid;
                int j = idx >> 3, q = idx & 7;
                ld[i] = *(const float4*)(Wg + j * Hv + k0n + q * 4);
            }
        }

        const int k0 = ch * KC;
#pragma unroll 4
        for (int kk = 0; kk < KC; ++kk) {
            float a[8], b[8];
#pragma unroll
            for (int r = 0; r < 8; ++r)          // broadcast within warp
                a[r] = sA[(row0 + r) * AS + k0 + kk];
#pragma unroll
            for (int c = 0; c < 8; ++c)          // bank = (lane+kk)%32, conflict-free
                b[c] = sW[(lane + 32 * c) * WKS + kk];
#pragma unroll
            for (int r = 0; r < 8; ++r)
#pragma unroll
                for (int c = 0; c < 8; ++c)
                    acc[r][c] = fmaf(a[r], b[c], acc[r][c]);
        }
        __syncthreads();
    }
}

__global__ void __launch_bounds__(NTHREADS, 1)
flexhnn_kernel(const float* __restrict__ z,
               const float* __restrict__ hW1, const float* __restrict__ hb1,
               const float* __restrict__ hW2, const float* __restrict__ hb2,
               const float* __restrict__ fW1, const float* __restrict__ fb1,
               const float* __restrict__ fW2, const float* __restrict__ fb2,
               const float* __restrict__ fW3, const float* __restrict__ fb3,
               float* __restrict__ out)
{
    extern __shared__ float sm[];
    float* sA   = sm;                       // BM*AS       activations
    float* sW   = sA   + BM * AS;           // Hv*WKS      weight K-chunk
    float* sZ   = sW   + Hv * WKS;          // BM*ZS       z tile
    float* sHW1 = sZ   + BM * ZS;           // Hv*ZS
    float* sFW1 = sHW1 + Hv * ZS;           // Hv*ZS
    float* sFW3 = sFW1 + Hv * ZS;           // DZv*AS
    float* sHB1 = sFW3 + DZv * AS;          // Hv
    float* sHB2 = sHB1 + Hv;
    float* sFB1 = sHB2 + Hv;
    float* sFB2 = sFB1 + Hv;
    float* sFB3 = sFB2 + Hv;                // DZv

    const int tid  = threadIdx.x;
    const int lane = tid & 31;
    const int wrp  = tid >> 5;
    const int row0 = wrp * 8;
    const long n0  = (long)blockIdx.x * BM;

    // ---- cooperative load of small weights / biases / z tile ----
    for (int i = tid; i < Hv * DZv; i += NTHREADS) {
        int j = i >> 4, d = i & 15;
        sHW1[j * ZS + d] = hW1[i];
        sFW1[j * ZS + d] = fW1[i];
    }
    for (int i = tid; i < DZv * Hv; i += NTHREADS) {
        int j = i >> 8, k = i & 255;
        sFW3[j * AS + k] = fW3[i];
    }
    {
        sHB1[tid] = hb1[tid]; sHB2[tid] = hb2[tid];
        sFB1[tid] = fb1[tid]; sFB2[tid] = fb2[tid];
        if (tid < DZv) sFB3[tid] = fb3[tid];
    }
    {
        float4 v = ((const float4*)(z + n0 * DZv))[tid];   // 64*16 floats = 256 float4
        int r = tid >> 2, c = (tid & 3) * 4;
        sZ[r * ZS + c + 0] = v.x; sZ[r * ZS + c + 1] = v.y;
        sZ[r * ZS + c + 2] = v.z; sZ[r * ZS + c + 3] = v.w;
    }
    __syncthreads();

    // ---- stage 1: t1 = tanh(z @ hW1^T + hb1) -> sA ----
#pragma unroll
    for (int r = 0; r < 8; ++r) {
        const int row = row0 + r;
        float zr[DZv];
#pragma unroll
        for (int d = 0; d < DZv; ++d) zr[d] = sZ[row * ZS + d];
#pragma unroll
        for (int c = 0; c < 8; ++c) {
            const int j = lane + 32 * c;
            float a = sHB1[j];
#pragma unroll
            for (int d = 0; d < DZv; ++d) a = fmaf(zr[d], sHW1[j * ZS + d], a);
            sA[row * AS + j] = fast_tanh(a);
        }
    }
    __syncthreads();

    float acc[8][8];

    // ---- GEMM2: a2 = t1 @ hW2^T ; epilogue -> g in sA ----
    big_gemm(hW2, sA, sW, tid, lane, row0, acc);
#pragma unroll
    for (int r = 0; r < 8; ++r) {
        const int row = row0 + r;
        float zr[DZv];
#pragma unroll
        for (int d = 0; d < DZv; ++d) zr[d] = sZ[row * ZS + d];
#pragma unroll
        for (int c = 0; c < 8; ++c) {
            const int j = lane + 32 * c;
            float t2 = fast_tanh(acc[r][c] + sHB2[j]);
            float s2 = 1.0f - t2 * t2;
            float f = sFB1[j];
#pragma unroll
            for (int d = 0; d < DZv; ++d) f = fmaf(zr[d], sFW1[j * ZS + d], f);
            sA[row * AS + j] = 0.5f * (f * s2) + 0.5f * fast_tanh(f);
        }
    }
    __syncthreads();

    // ---- GEMM3: f2 = g @ fW2^T ; epilogue (s1 recomputed from z) -> h in sA ----
    big_gemm(fW2, sA, sW, tid, lane, row0, acc);
#pragma unroll
    for (int r = 0; r < 8; ++r) {
        const int row = row0 + r;
        float zr[DZv];
#pragma unroll
        for (int d = 0; d < DZv; ++d) zr[d] = sZ[row * ZS + d];
#pragma unroll
        for (int c = 0; c < 8; ++c) {
            const int j = lane + 32 * c;
            float a1 = sHB1[j];
#pragma unroll
            for (int d = 0; d < DZv; ++d) a1 = fmaf(zr[d], sHW1[j * ZS + d], a1);
            float t1v = fast_tanh(a1);
            float s1 = 1.0f - t1v * t1v;
            float f2 = acc[r][c] + sFB2[j];
            sA[row * AS + j] = 0.5f * (f2 * s1) + 0.5f * fast_tanh(f2);
        }
    }
    __syncthreads();

    // ---- GEMM4: o = h @ fW3^T + fb3 ; symplectic swap -> out ----
    {
        const int j16  = lane & 15;
        const int rsub = (lane >> 4) * 4;
        const float* wrow = sFW3 + j16 * AS;
        const float* a0 = sA + (row0 + rsub + 0) * AS;
        const float* a1 = sA + (row0 + rsub + 1) * AS;
        const float* a2 = sA + (row0 + rsub + 2) * AS;
        const float* a3 = sA + (row0 + rsub + 3) * AS;
        float b = sFB3[j16];
        float o0 = b, o1 = b, o2 = b, o3 = b;
#pragma unroll 8
        for (int k = 0; k < Hv; ++k) {
            float w = wrow[k];
            o0 = fmaf(a0[k], w, o0);
            o1 = fmaf(a1[k], w, o1);
            o2 = fmaf(a2[k], w, o2);
            o3 = fmaf(a3[k], w, o3);
        }
        // dz[:, :8] = o[:, 8:] ; dz[:, 8:] = -o[:, :8]
        const int dst = (j16 + 8) & 15;
        const float sgn = (j16 < 8) ? -1.0f : 1.0f;
        const long base = (n0 + row0 + rsub) * DZv;
        out[base + 0 * DZv + dst] = sgn * o0;
        out[base + 1 * DZv + dst] = sgn * o1;
        out[base + 2 * DZv + dst] = sgn * o2;
        out[base + 3 * DZv + dst] = sgn * o3;
    }
}

extern "C" void kernel_launch(void* const* d_in, const int* in_sizes, int n_in,
                              void* d_out, int out_size)
{
    // metadata order: t, z, hW1, hb1, hW2, hb2, fW1, fb1, fW2, fb2, fW3, fb3
    const float* z   = (const float*)d_in[1];
    const float* hW1 = (const float*)d_in[2];
    const float* hb1 = (const float*)d_in[3];
    const float* hW2 = (const float*)d_in[4];
    const float* hb2 = (const float*)d_in[5];
    const float* fW1 = (const float*)d_in[6];
    const float* fb1 = (const float*)d_in[7];
    const float* fW2 = (const float*)d_in[8];
    const float* fb2 = (const float*)d_in[9];
    const float* fW3 = (const float*)d_in[10];
    const float* fb3 = (const float*)d_in[11];
    float* out = (float*)d_out;

    const int n = in_sizes[1] / DZv;     // 131072 rows
    const int grid = n / BM;             // 2048 blocks

    const int smem_bytes =
        (BM * AS + Hv * WKS + BM * ZS + 2 * Hv * ZS + DZv * AS + 4 * Hv + DZv)
        * (int)sizeof(float);            // ~159.4 KB

    cudaFuncSetAttribute(flexhnn_kernel,
                         cudaFuncAttributeMaxDynamicSharedMemorySize, smem_bytes);

    flexhnn_kernel<<<grid, NTHREADS, smem_bytes>>>(
        z, hW1, hb1, hW2, hb2, fW1, fb1, fW2, fb2, fW3, fb3, out);
}

// round 4
// speedup vs baseline: 1.4815x; 1.4815x over previous
#include <cuda_runtime.h>
#include <cstdint>

#define NT 512
#define BM 128

// Pre-rounded (tf32-rna), bank-swizzled copies of hW2 / fW2:
// layout [g][ch][n][k_sw], k_sw = k ^ (2*(n&7)), 16 k per chunk.  512 KB.
__device__ float g_wsw[2 * 16 * 256 * 16];

// ---- smem layout (float indices) ----
#define F_SA    0          // 128 x 256, XOR-swizzled: phys_col = col ^ (4*(row&7))
#define F_RING  32768      // 2 x [256][16] W-chunk ring (pre-swizzled)
#define F_Z     40960      // 128 x 16 raw fp32 z
#define F_HW1T  43008      // hW1 transposed [16][256]
#define F_FW1T  47104      // fW1 transposed [16][256]
#define F_FW3T  51200      // fW3 transposed [256][16]
#define F_HB1   55296
#define F_HB2   55552
#define F_FB1   55808
#define F_FB2   56064
#define F_FB3   56320
#define F_TOTAL 56336      // floats -> 225,344 bytes

#define CP_ASYNC16(d, s) \
    asm volatile("cp.async.cg.shared.global [%0], [%1], 16;" :: "r"(d), "l"(s))
#define CP_COMMIT() asm volatile("cp.async.commit_group;")
#define CP_WAIT1()  asm volatile("cp.async.wait_group 1;")
#define CP_WAIT0()  asm volatile("cp.async.wait_group 0;")

__device__ __forceinline__ uint32_t smem_u32(const void* p) {
    uint32_t a;
    asm("{ .reg .u64 t; cvta.to.shared.u64 t, %1; cvt.u32.u64 %0, t; }" : "=r"(a) : "l"(p));
    return a;
}
__device__ __forceinline__ float fast_tanh(float x) {
    float e = __expf(2.0f * x);
    return 1.0f - 2.0f / (e + 1.0f);
}
__device__ __forceinline__ float tf32r(float x) {
    uint32_t u; asm("cvt.rna.tf32.f32 %0, %1;" : "=r"(u) : "f"(x));
    return __uint_as_float(u);
}
__device__ __forceinline__ void mma8(float d[4], const uint32_t a[4],
                                     uint32_t b0, uint32_t b1) {
    asm volatile("mma.sync.aligned.m16n8k8.row.col.f32.tf32.tf32.f32 "
                 "{%0,%1,%2,%3},{%4,%5,%6,%7},{%8,%9},{%0,%1,%2,%3};"
                 : "+f"(d[0]), "+f"(d[1]), "+f"(d[2]), "+f"(d[3])
                 : "r"(a[0]), "r"(a[1]), "r"(a[2]), "r"(a[3]), "r"(b0), "r"(b1));
}

// ---------- pre-round kernel: hW2/fW2 -> tf32-rounded swizzled scratch ----------
__global__ void __launch_bounds__(NT) preround_kernel(const float* __restrict__ hW2,
                                                      const float* __restrict__ fW2) {
    int idx = blockIdx.x * NT + threadIdx.x;       // 0 .. 131071
    int g = idx >> 16, e = idx & 65535;
    int n = e >> 8, kg = e & 255;
    const float* W = g ? fW2 : hW2;
    float v = tf32r(W[n * 256 + kg]);
    int ch = kg >> 4, k = kg & 15;
    g_wsw[(((g * 16 + ch) * 256 + n) << 4) + (k ^ (2 * (n & 7)))] = v;
}

// ---------- main kernel ----------
__global__ void __launch_bounds__(NT, 1)
flexhnn_mma(const float* __restrict__ z,
            const float* __restrict__ hW1, const float* __restrict__ hb1,
            const float* __restrict__ hb2,
            const float* __restrict__ fW1, const float* __restrict__ fb1,
            const float* __restrict__ fb2,
            const float* __restrict__ fW3, const float* __restrict__ fb3,
            float* __restrict__ out)
{
    extern __shared__ float sm[];
    uint32_t* smu = (uint32_t*)sm;
    const int t = threadIdx.x, lane = t & 31, w = t >> 5;
    const long n0 = (long)blockIdx.x * BM;

    // GEMM warp tiling: warp -> 32-row strip x 64-col quarter
    const int mrow = (w & 3) * 32;
    const int nq   = (w >> 2) * 64;
    const int fr   = lane >> 2;       // fragment row group 0..7
    const int fc   = lane & 3;        // fragment k/col 0..3
    const int xor4 = fr << 2;

    // epilogue mapping: thread -> 1 row, interleaved 4-col groups
    const int erow = t >> 2, ecg = t & 3, er7 = erow & 7;

    const uint32_t ring_u32 = smem_u32(sm + F_RING);

    // ---------------- stage ----------------
    {   // z tile (raw fp32)
        float4 v = *(const float4*)(z + (n0 + (t >> 2)) * 16 + (t & 3) * 4);
        *(float4*)(sm + F_Z + (t >> 2) * 16 + (t & 3) * 4) = v;
    }
#pragma unroll
    for (int p = 0; p < 2; ++p) {
        int idx = p * NT + t;                      // 0..1023
        int j = idx >> 2, d4 = (idx & 3) << 2;
        float4 a = *(const float4*)(hW1 + j * 16 + d4);
        sm[F_HW1T + (d4 + 0) * 256 + j] = a.x;
        sm[F_HW1T + (d4 + 1) * 256 + j] = a.y;
        sm[F_HW1T + (d4 + 2) * 256 + j] = a.z;
        sm[F_HW1T + (d4 + 3) * 256 + j] = a.w;
        float4 b = *(const float4*)(fW1 + j * 16 + d4);
        sm[F_FW1T + (d4 + 0) * 256 + j] = b.x;
        sm[F_FW1T + (d4 + 1) * 256 + j] = b.y;
        sm[F_FW1T + (d4 + 2) * 256 + j] = b.z;
        sm[F_FW1T + (d4 + 3) * 256 + j] = b.w;
        int jj = idx >> 6, k4 = (idx & 63) << 2;
        float4 c = *(const float4*)(fW3 + jj * 256 + k4);
        sm[F_FW3T + (k4 + 0) * 16 + jj] = c.x;
        sm[F_FW3T + (k4 + 1) * 16 + jj] = c.y;
        sm[F_FW3T + (k4 + 2) * 16 + jj] = c.z;
        sm[F_FW3T + (k4 + 3) * 16 + jj] = c.w;
    }
    if (t < 256) {
        sm[F_HB1 + t] = hb1[t]; sm[F_HB2 + t] = hb2[t];
        sm[F_FB1 + t] = fb1[t]; sm[F_FB2 + t] = fb2[t];
    }
    if (t < 16) sm[F_FB3 + t] = fb3[t];

    // issue W chunks 0,1 (each thread: 2 x 16B)
    const int cn = t >> 1, cq = (t & 1) * 2;
#pragma unroll
    for (int cc = 0; cc < 2; ++cc) {
        const float* src = g_wsw + (((size_t)cc * 256 + cn) << 4) + cq * 4;
        uint32_t dst = ring_u32 + (((cc & 1) * 4096 + cn * 16 + cq * 4) << 2);
        CP_ASYNC16(dst, src);
        CP_ASYNC16(dst + 16, src + 4);
        CP_COMMIT();
    }
    __syncthreads();

    // ---------------- epi1: t1 = tanh(z @ hW1^T + hb1) -> sA (tf32) ----------------
    float zr[16];
#pragma unroll
    for (int q = 0; q < 4; ++q) {
        float4 v = *(const float4*)(sm + F_Z + erow * 16 + q * 4);
        zr[q * 4] = v.x; zr[q * 4 + 1] = v.y; zr[q * 4 + 2] = v.z; zr[q * 4 + 3] = v.w;
    }
    for (int m = 0; m < 16; ++m) {
        int j0 = ecg * 4 + m * 16;
        float o[4];
#pragma unroll
        for (int e = 0; e < 4; ++e) {
            int j = j0 + e;
            float a = sm[F_HB1 + j];
#pragma unroll
            for (int d = 0; d < 16; ++d) a = fmaf(zr[d], sm[F_HW1T + d * 256 + j], a);
            o[e] = tf32r(fast_tanh(a));
        }
        *(float4*)(sm + F_SA + erow * 256 + (j0 ^ (er7 << 2))) =
            make_float4(o[0], o[1], o[2], o[3]);
    }
    __syncthreads();

    // ---------------- GEMM2 + epi2 + GEMM3, chunked ----------------
    float acc[2][8][4];

    for (int cc = 0; cc < 32; ++cc) {
        if (cc < 31) { CP_WAIT1(); } else { CP_WAIT0(); }
        __syncthreads();

        if ((cc & 15) == 0) {
#pragma unroll
            for (int mt = 0; mt < 2; ++mt)
#pragma unroll
                for (int nt = 0; nt < 8; ++nt)
#pragma unroll
                    for (int i = 0; i < 4; ++i) acc[mt][nt][i] = 0.0f;
        }

        {   // compute chunk cc (16 k-cols = 2 k-steps)
            const uint32_t* rb = smu + F_RING + (cc & 1) * 4096;
            const int kbase = (cc & 15) * 16;
#pragma unroll
            for (int ks = 0; ks < 2; ++ks) {
                const int kc = kbase + ks * 8;
                uint32_t a[2][4];
#pragma unroll
                for (int mt = 0; mt < 2; ++mt) {
                    int r0 = mrow + mt * 16 + fr;
                    int c0 = kc + fc;
                    a[mt][0] = smu[F_SA + r0 * 256 + (c0 ^ xor4)];
                    a[mt][1] = smu[F_SA + (r0 + 8) * 256 + (c0 ^ xor4)];
                    a[mt][2] = smu[F_SA + r0 * 256 + ((c0 + 4) ^ xor4)];
                    a[mt][3] = smu[F_SA + (r0 + 8) * 256 + ((c0 + 4) ^ xor4)];
                }
#pragma unroll
                for (int nt = 0; nt < 8; ++nt) {
                    int n = nq + nt * 8 + fr;
                    int sw = 2 * (n & 7);
                    uint32_t b0 = rb[n * 16 + ((ks * 8 + fc) ^ sw)];
                    uint32_t b1 = rb[n * 16 + ((ks * 8 + fc + 4) ^ sw)];
                    mma8(acc[0][nt], a[0], b0, b1);
                    mma8(acc[1][nt], a[1], b0, b1);
                }
            }
        }
        __syncthreads();

        if (cc + 2 < 32) {   // prefetch chunk cc+2 into the slot just freed
            const float* src = g_wsw + (((size_t)(cc + 2) * 256 + cn) << 4) + cq * 4;
            uint32_t dst = ring_u32 + ((((cc + 2) & 1) * 4096 + cn * 16 + cq * 4) << 2);
            CP_ASYNC16(dst, src);
            CP_ASYNC16(dst + 16, src + 4);
            CP_COMMIT();
        }

        if (cc == 15) {
            // ---- store a2 raw -> sA ----
#pragma unroll
            for (int mt = 0; mt < 2; ++mt)
#pragma unroll
                for (int nt = 0; nt < 8; ++nt) {
                    int r0 = mrow + mt * 16 + fr;
                    int col = nq + nt * 8 + 2 * fc;
                    int ph = col ^ xor4;
                    *(float2*)(sm + F_SA + r0 * 256 + ph) =
                        make_float2(acc[mt][nt][0], acc[mt][nt][1]);
                    *(float2*)(sm + F_SA + (r0 + 8) * 256 + ph) =
                        make_float2(acc[mt][nt][2], acc[mt][nt][3]);
                }
            __syncthreads();
            // ---- epi2: g = .5*f*s2 + .5*tanh(f),  f = z@fW1^T+fb1 ----
            for (int m = 0; m < 16; ++m) {
                int j0 = ecg * 4 + m * 16;
                float* pa = sm + F_SA + erow * 256 + (j0 ^ (er7 << 2));
                float4 v = *(float4*)pa;
                float* ve = &v.x;
#pragma unroll
                for (int e = 0; e < 4; ++e) {
                    int j = j0 + e;
                    float t2 = fast_tanh(ve[e] + sm[F_HB2 + j]);
                    float s2 = 1.0f - t2 * t2;
                    float f = sm[F_FB1 + j];
#pragma unroll
                    for (int d = 0; d < 16; ++d)
                        f = fmaf(zr[d], sm[F_FW1T + d * 256 + j], f);
                    ve[e] = tf32r(0.5f * (f * s2) + 0.5f * fast_tanh(f));
                }
                *(float4*)pa = v;
            }
            __syncthreads();
        }
    }

    // ---- store f2 raw -> sA ----
#pragma unroll
    for (int mt = 0; mt < 2; ++mt)
#pragma unroll
        for (int nt = 0; nt < 8; ++nt) {
            int r0 = mrow + mt * 16 + fr;
            int col = nq + nt * 8 + 2 * fc;
            int ph = col ^ xor4;
            *(float2*)(sm + F_SA + r0 * 256 + ph) =
                make_float2(acc[mt][nt][0], acc[mt][nt][1]);
            *(float2*)(sm + F_SA + (r0 + 8) * 256 + ph) =
                make_float2(acc[mt][nt][2], acc[mt][nt][3]);
        }
    __syncthreads();

    // ---- epi3: h = .5*f2*s1 + .5*tanh(f2), s1 recomputed from z ----
    for (int m = 0; m < 16; ++m) {
        int j0 = ecg * 4 + m * 16;
        float* pa = sm + F_SA + erow * 256 + (j0 ^ (er7 << 2));
        float4 v = *(float4*)pa;
        float* ve = &v.x;
#pragma unroll
        for (int e = 0; e < 4; ++e) {
            int j = j0 + e;
            float a1 = sm[F_HB1 + j];
#pragma unroll
            for (int d = 0; d < 16; ++d)
                a1 = fmaf(zr[d], sm[F_HW1T + d * 256 + j], a1);
            float t1 = fast_tanh(a1);
            float s1 = 1.0f - t1 * t1;
            float f2 = ve[e] + sm[F_FB2 + j];
            ve[e] = 0.5f * (f2 * s1) + 0.5f * fast_tanh(f2);   // fp32, SIMT GEMM4 next
        }
        *(float4*)pa = v;
    }
    __syncthreads();

    // ---- GEMM4 (SIMT): o = h @ fW3^T + fb3; symplectic swap -> out ----
    {
        const int jg = t & 3, row = t >> 2, r7 = row & 7;
        float o0 = sm[F_FB3 + jg * 4 + 0];
        float o1 = sm[F_FB3 + jg * 4 + 1];
        float o2 = sm[F_FB3 + jg * 4 + 2];
        float o3 = sm[F_FB3 + jg * 4 + 3];
#pragma unroll 8
        for (int c4 = 0; c4 < 64; ++c4) {
            float4 h4 = *(const float4*)(sm + F_SA + row * 256 + ((c4 ^ r7) << 2));
            const float* he = &h4.x;
#pragma unroll
            for (int kk = 0; kk < 4; ++kk) {
                int k = c4 * 4 + kk;
                float4 w4 = *(const float4*)(sm + F_FW3T + k * 16 + jg * 4);
                float hv = he[kk];
                o0 = fmaf(hv, w4.x, o0);
                o1 = fmaf(hv, w4.y, o1);
                o2 = fmaf(hv, w4.z, o2);
                o3 = fmaf(hv, w4.w, o3);
            }
        }
        float o[4] = {o0, o1, o2, o3};
        float* po = out + (n0 + row) * 16;
#pragma unroll
        for (int e = 0; e < 4; ++e) {
            int j = jg * 4 + e;
            int dst = (j + 8) & 15;
            po[dst] = (j < 8) ? -o[e] : o[e];
        }
    }
}

extern "C" void kernel_launch(void* const* d_in, const int* in_sizes, int n_in,
                              void* d_out, int out_size)
{
    // metadata order: t, z, hW1, hb1, hW2, hb2, fW1, fb1, fW2, fb2, fW3, fb3
    const float* z   = (const float*)d_in[1];
    const float* hW1 = (const float*)d_in[2];
    const float* hb1 = (const float*)d_in[3];
    const float* hW2 = (const float*)d_in[4];
    const float* hb2 = (const float*)d_in[5];
    const float* fW1 = (const float*)d_in[6];
    const float* fb1 = (const float*)d_in[7];
    const float* fW2 = (const float*)d_in[8];
    const float* fb2 = (const float*)d_in[9];
    const float* fW3 = (const float*)d_in[10];
    const float* fb3 = (const float*)d_in[11];
    float* out = (float*)d_out;

    const int n = in_sizes[1] / 16;          // 131072 rows
    const int grid = n / BM;                 // 1024 CTAs

    preround_kernel<<<256, NT>>>(hW2, fW2);

    const int smem_bytes = F_TOTAL * (int)sizeof(float);   // 225,344
    cudaFuncSetAttribute(flexhnn_mma,
                         cudaFuncAttributeMaxDynamicSharedMemorySize, smem_bytes);
    flexhnn_mma<<<grid, NT, smem_bytes>>>(
        z, hW1, hb1, hb2, fW1, fb1, fb2, fW3, fb3, out);
}

// round 5
// speedup vs baseline: 2.2097x; 1.4915x over previous
#include <cuda_runtime.h>
#include <cuda_fp16.h>
#include <cstdint>

#define NT 512
#define BM 128

// fp16 fragment-packed weights: [hW2 | fW2 | fW3], written by prepack kernel.
// Per big GEMM: idx = ((kk*32+nf)*32+lane)*2+br  (32768 u32 = 128KB each).
// fW3: idx = 65536 + ((kk*2+nf)*32+lane)*2+br (2048 u32).
__device__ __align__(16) uint32_t g_wpk[2 * 32768 + 2048];

// ---- smem byte offsets ----
#define O_W    0u        // 128KB weight buffer (fragment-packed fp16)
#define O_SA   131072u   // 64KB activations, fragment-major half2
#define O_WH   196608u   // hW1^T [16][256] f32
#define O_WF   212992u   // fW1^T [16][256] f32; later fW3 frags (8KB)
#define O_HB1  229376u   // hb1 f32[256]
#define O_HB2  230400u   // hb2 half[256]
#define O_FB1  230912u   // fb1 half[256]
#define O_FB2  231424u   // fb2 half[256]
#define O_FB3  231936u   // fb3 f32[16]
#define SMEMB  232000

#define CP_ASYNC16(d, s) \
    asm volatile("cp.async.cg.shared.global [%0], [%1], 16;" :: "r"(d), "l"(s))
#define CP_COMMIT() asm volatile("cp.async.commit_group;")
#define CP_WAIT0()  asm volatile("cp.async.wait_group 0;")

__device__ __forceinline__ uint32_t smem_u32(const void* p) {
    uint32_t a;
    asm("{ .reg .u64 t; cvta.to.shared.u64 t, %1; cvt.u32.u64 %0, t; }" : "=r"(a) : "l"(p));
    return a;
}
__device__ __forceinline__ float fast_tanh(float x) {
    float e = __expf(2.0f * x);
    return 1.0f - 2.0f / (e + 1.0f);
}
__device__ __forceinline__ uint32_t h2u(float lo, float hi) {
    uint32_t r;
    asm("{ .reg .b16 l, h; cvt.rn.f16.f32 l, %1; cvt.rn.f16.f32 h, %2; mov.b32 %0, {l, h}; }"
        : "=r"(r) : "f"(lo), "f"(hi));
    return r;
}
__device__ __forceinline__ void mma16816(float d[4],
    uint32_t a0, uint32_t a1, uint32_t a2, uint32_t a3, uint32_t b0, uint32_t b1) {
    asm volatile("mma.sync.aligned.m16n8k16.row.col.f32.f16.f16.f32 "
                 "{%0,%1,%2,%3},{%4,%5,%6,%7},{%8,%9},{%0,%1,%2,%3};"
                 : "+f"(d[0]), "+f"(d[1]), "+f"(d[2]), "+f"(d[3])
                 : "r"(a0), "r"(a1), "r"(a2), "r"(a3), "r"(b0), "r"(b1));
}

// ---------- prepack: hW2/fW2/fW3 -> fp16 fragment order ----------
__global__ void __launch_bounds__(NT) prepack(const float* __restrict__ hW2,
                                              const float* __restrict__ fW2,
                                              const float* __restrict__ fW3) {
    int tid = blockIdx.x * NT + threadIdx.x;
    if (tid < 65536) {
        int off = tid & 32767;
        const float* W = (tid >> 15) ? fW2 : hW2;
        int br = off & 1, lane = (off >> 1) & 31, nf = (off >> 6) & 31, kk = off >> 11;
        int n = nf * 8 + (lane >> 2), k = kk * 16 + 2 * (lane & 3) + br * 8;
        g_wpk[tid] = h2u(W[n * 256 + k], W[n * 256 + k + 1]);
    } else if (tid < 67584) {
        int off = tid - 65536;
        int br = off & 1, lane = (off >> 1) & 31, nf = (off >> 6) & 1, kk = off >> 7;
        int n = nf * 8 + (lane >> 2), k = kk * 16 + 2 * (lane & 3) + br * 8;
        g_wpk[tid] = h2u(fW3[n * 256 + k], fW3[n * 256 + k + 1]);
    }
}

// big GEMM: acc[2][8][4] += A(sA frags, warp rows) * B(Wbuf frags)
__device__ __forceinline__ void gemm_big(const uint4* __restrict__ sa4,
                                         const uint2* __restrict__ wb2,
                                         int w, int lane, float acc[2][8][4]) {
    const int s0 = (w & 3) * 2, nfb = (w >> 2) * 8;
#pragma unroll
    for (int kk = 0; kk < 16; ++kk) {
        uint4 A0 = sa4[(s0 * 16 + kk) * 32 + lane];
        uint4 A1 = sa4[((s0 + 1) * 16 + kk) * 32 + lane];
#pragma unroll
        for (int nt = 0; nt < 8; ++nt) {
            uint2 B = wb2[(kk * 32 + nfb + nt) * 32 + lane];
            mma16816(acc[0][nt], A0.x, A0.y, A0.z, A0.w, B.x, B.y);
            mma16816(acc[1][nt], A1.x, A1.y, A1.z, A1.w, B.x, B.y);
        }
    }
}

__global__ void __launch_bounds__(NT, 1)
flexhnn_f16(const float* __restrict__ z,
            const float* __restrict__ hW1, const float* __restrict__ hb1,
            const float* __restrict__ hb2,
            const float* __restrict__ fW1, const float* __restrict__ fb1,
            const float* __restrict__ fb2, const float* __restrict__ fb3,
            float* __restrict__ out)
{
    extern __shared__ __align__(16) char smx[];
    const uint32_t smb = smem_u32(smx);
    uint32_t* smU = (uint32_t*)smx;
    float*    smF = (float*)smx;
    const uint4* sa4 = (const uint4*)(smx + O_SA);
    const uint2* wb2 = (const uint2*)(smx + O_W);

    const int t = threadIdx.x, lane = t & 31, w = t >> 5;
    const int fr = lane >> 2, fc = lane & 3;
    const int nq = (w >> 2) * 64;
    const long n0 = (long)blockIdx.x * BM;

    // ---------------- stage ----------------
    // Wbuf <- hW2 frags (128KB)
#pragma unroll
    for (int p = 0; p < 16; ++p) {
        uint32_t dst = smb + O_W + (uint32_t)(p * NT + t) * 16u;
        CP_ASYNC16(dst, (const char*)g_wpk + (p * NT + t) * 16);
    }
    CP_COMMIT();
    // hW1^T, fW1^T (f32)
#pragma unroll
    for (int p = 0; p < 2; ++p) {
        int idx = p * NT + t;                // 0..1023 float4s
        int j = idx >> 2, d4 = (idx & 3) * 4;
        float4 a = *(const float4*)(hW1 + j * 16 + d4);
        smF[O_WH / 4 + (d4 + 0) * 256 + j] = a.x;
        smF[O_WH / 4 + (d4 + 1) * 256 + j] = a.y;
        smF[O_WH / 4 + (d4 + 2) * 256 + j] = a.z;
        smF[O_WH / 4 + (d4 + 3) * 256 + j] = a.w;
        float4 b = *(const float4*)(fW1 + j * 16 + d4);
        smF[O_WF / 4 + (d4 + 0) * 256 + j] = b.x;
        smF[O_WF / 4 + (d4 + 1) * 256 + j] = b.y;
        smF[O_WF / 4 + (d4 + 2) * 256 + j] = b.z;
        smF[O_WF / 4 + (d4 + 3) * 256 + j] = b.w;
    }
    if (t < 256) {
        smF[O_HB1 / 4 + t] = hb1[t];
        ((__half*)(smx + O_HB2))[t] = __float2half(hb2[t]);
        ((__half*)(smx + O_FB1))[t] = __float2half(fb1[t]);
        ((__half*)(smx + O_FB2))[t] = __float2half(fb2[t]);
    }
    if (t < 16) smF[O_FB3 / 4 + t] = fb3[t];
    __syncthreads();

    // ---------------- epi1: t1 = tanh(z @ hW1^T + hb1) -> sA frags ----------------
    {
        const int r0 = (t >> 4) * 4, cp2 = t & 15;
        float4 z4[4][4];
#pragma unroll
        for (int i = 0; i < 4; ++i)
#pragma unroll
            for (int q = 0; q < 4; ++q)
                z4[i][q] = *(const float4*)(z + (n0 + r0 + i) * 16 + q * 4);
#pragma unroll
        for (int p = 0; p < 8; ++p) {
            const int c0 = p * 32 + cp2 * 2;
            float fa[4][2];
            const float b0 = smF[O_HB1 / 4 + c0], b1 = smF[O_HB1 / 4 + c0 + 1];
#pragma unroll
            for (int i = 0; i < 4; ++i) { fa[i][0] = b0; fa[i][1] = b1; }
#pragma unroll
            for (int d = 0; d < 16; ++d) {
                float2 wv = *(const float2*)(smF + O_WH / 4 + d * 256 + c0);
#pragma unroll
                for (int i = 0; i < 4; ++i) {
                    float zv = ((const float*)&z4[i][d >> 2])[d & 3];
                    fa[i][0] = fmaf(zv, wv.x, fa[i][0]);
                    fa[i][1] = fmaf(zv, wv.y, fa[i][1]);
                }
            }
            const int kk = c0 >> 4, cp = (c0 & 15) >> 1;
            const int slotc = (cp >= 4) ? 2 : 0, fcc = cp & 3;
#pragma unroll
            for (int i = 0; i < 4; ++i) {
                int r = r0 + i;
                uint32_t v = h2u(fast_tanh(fa[i][0]), fast_tanh(fa[i][1]));
                int strip = r >> 4;
                int lanep = (r & 7) * 4 + fcc;
                int slot = ((r & 15) >> 3) + slotc;
                smU[O_SA / 4 + ((strip * 16 + kk) * 32 + lanep) * 4 + slot] = v;
            }
        }
    }
    CP_WAIT0();
    __syncthreads();

    // ---------------- GEMM2: a2 = t1 @ hW2^T ----------------
    float acc[2][8][4];
#pragma unroll
    for (int mt = 0; mt < 2; ++mt)
#pragma unroll
        for (int nt = 0; nt < 8; ++nt)
#pragma unroll
            for (int i = 0; i < 4; ++i) acc[mt][nt][i] = 0.0f;
    gemm_big(sa4, wb2, w, lane, acc);
    __syncthreads();                         // all Wbuf reads done

    // Wbuf <- fW2 frags (overlaps epi2)
#pragma unroll
    for (int p = 0; p < 16; ++p) {
        uint32_t dst = smb + O_W + (uint32_t)(p * NT + t) * 16u;
        CP_ASYNC16(dst, (const char*)g_wpk + 131072 + (p * NT + t) * 16);
    }
    CP_COMMIT();

    // ---------------- epi2 (register): g = .5*f*s2 + .5*tanh(f) -> sA ----------------
    {
        const __half* hb2h = (const __half*)(smx + O_HB2);
        const __half* fb1h = (const __half*)(smx + O_FB1);
#pragma unroll
        for (int mt = 0; mt < 2; ++mt) {
            const int rbase = (w & 3) * 32 + mt * 16;
            const int strip = (w & 3) * 2 + mt;
            float4 zlo[4], zhi[4];
#pragma unroll
            for (int q = 0; q < 4; ++q) {
                zlo[q] = *(const float4*)(z + (n0 + rbase + fr) * 16 + q * 4);
                zhi[q] = *(const float4*)(z + (n0 + rbase + fr + 8) * 16 + q * 4);
            }
#pragma unroll
            for (int nt = 0; nt < 8; ++nt) {
                const int c0 = nq + nt * 8 + 2 * fc;
                float fb0 = __half2float(fb1h[c0]), fb1v = __half2float(fb1h[c0 + 1]);
                float f00 = fb0, f01 = fb1v, f10 = fb0, f11 = fb1v;
#pragma unroll
                for (int d = 0; d < 16; ++d) {
                    float2 wv = *(const float2*)(smF + O_WF / 4 + d * 256 + c0);
                    float zl = ((const float*)&zlo[d >> 2])[d & 3];
                    float zh = ((const float*)&zhi[d >> 2])[d & 3];
                    f00 = fmaf(zl, wv.x, f00); f01 = fmaf(zl, wv.y, f01);
                    f10 = fmaf(zh, wv.x, f10); f11 = fmaf(zh, wv.y, f11);
                }
                const float hb0 = __half2float(hb2h[c0]), hb1v = __half2float(hb2h[c0 + 1]);
                const int kkc = (w >> 2) * 4 + (nt >> 1);
                const int sbase = (nt & 1) * 2;
                {   // row fr
                    float t2a = fast_tanh(acc[mt][nt][0] + hb0);
                    float t2b = fast_tanh(acc[mt][nt][1] + hb1v);
                    float g0 = 0.5f * (f00 * (1.0f - t2a * t2a)) + 0.5f * fast_tanh(f00);
                    float g1 = 0.5f * (f01 * (1.0f - t2b * t2b)) + 0.5f * fast_tanh(f01);
                    smU[O_SA / 4 + ((strip * 16 + kkc) * 32 + lane) * 4 + sbase] = h2u(g0, g1);
                }
                {   // row fr+8
                    float t2a = fast_tanh(acc[mt][nt][2] + hb0);
                    float t2b = fast_tanh(acc[mt][nt][3] + hb1v);
                    float g0 = 0.5f * (f10 * (1.0f - t2a * t2a)) + 0.5f * fast_tanh(f10);
                    float g1 = 0.5f * (f11 * (1.0f - t2b * t2b)) + 0.5f * fast_tanh(f11);
                    smU[O_SA / 4 + ((strip * 16 + kkc) * 32 + lane) * 4 + sbase + 1] = h2u(g0, g1);
                }
            }
        }
    }
    __syncthreads();                          // epi2 sA writes + wmvF reads done

    // fW3 frags -> O_WF region (8KB)
    {
        uint32_t dst = smb + O_WF + (uint32_t)t * 16u;
        CP_ASYNC16(dst, (const char*)g_wpk + 262144 + t * 16);
        CP_COMMIT();
    }
    CP_WAIT0();                               // fW2 + fW3 complete
    __syncthreads();

    // ---------------- GEMM3: f2 = g @ fW2^T ----------------
#pragma unroll
    for (int mt = 0; mt < 2; ++mt)
#pragma unroll
        for (int nt = 0; nt < 8; ++nt)
#pragma unroll
            for (int i = 0; i < 4; ++i) acc[mt][nt][i] = 0.0f;
    gemm_big(sa4, wb2, w, lane, acc);
    __syncthreads();                          // others' sA reads done before we overwrite

    // ---------------- epi3 (register): h = .5*f2*s1 + .5*tanh(f2) -> sA ----------------
    {
        const __half* fb2h = (const __half*)(smx + O_FB2);
#pragma unroll
        for (int mt = 0; mt < 2; ++mt) {
            const int rbase = (w & 3) * 32 + mt * 16;
            const int strip = (w & 3) * 2 + mt;
            float4 zlo[4], zhi[4];
#pragma unroll
            for (int q = 0; q < 4; ++q) {
                zlo[q] = *(const float4*)(z + (n0 + rbase + fr) * 16 + q * 4);
                zhi[q] = *(const float4*)(z + (n0 + rbase + fr + 8) * 16 + q * 4);
            }
#pragma unroll
            for (int nt = 0; nt < 8; ++nt) {
                const int c0 = nq + nt * 8 + 2 * fc;
                float ab0 = smF[O_HB1 / 4 + c0], ab1 = smF[O_HB1 / 4 + c0 + 1];
                float a00 = ab0, a01 = ab1, a10 = ab0, a11 = ab1;   // a1 matvec
#pragma unroll
                for (int d = 0; d < 16; ++d) {
                    float2 wv = *(const float2*)(smF + O_WH / 4 + d * 256 + c0);
                    float zl = ((const float*)&zlo[d >> 2])[d & 3];
                    float zh = ((const float*)&zhi[d >> 2])[d & 3];
                    a00 = fmaf(zl, wv.x, a00); a01 = fmaf(zl, wv.y, a01);
                    a10 = fmaf(zh, wv.x, a10); a11 = fmaf(zh, wv.y, a11);
                }
                const float b0 = __half2float(fb2h[c0]), b1 = __half2float(fb2h[c0 + 1]);
                const int kkc = (w >> 2) * 4 + (nt >> 1);
                const int sbase = (nt & 1) * 2;
                {
                    float t1a = fast_tanh(a00), t1b = fast_tanh(a01);
                    float x0 = acc[mt][nt][0] + b0, x1 = acc[mt][nt][1] + b1;
                    float h0 = 0.5f * (x0 * (1.0f - t1a * t1a)) + 0.5f * fast_tanh(x0);
                    float h1 = 0.5f * (x1 * (1.0f - t1b * t1b)) + 0.5f * fast_tanh(x1);
                    smU[O_SA / 4 + ((strip * 16 + kkc) * 32 + lane) * 4 + sbase] = h2u(h0, h1);
                }
                {
                    float t1a = fast_tanh(a10), t1b = fast_tanh(a11);
                    float x0 = acc[mt][nt][2] + b0, x1 = acc[mt][nt][3] + b1;
                    float h0 = 0.5f * (x0 * (1.0f - t1a * t1a)) + 0.5f * fast_tanh(x0);
                    float h1 = 0.5f * (x1 * (1.0f - t1b * t1b)) + 0.5f * fast_tanh(x1);
                    smU[O_SA / 4 + ((strip * 16 + kkc) * 32 + lane) * 4 + sbase + 1] = h2u(h0, h1);
                }
            }
        }
    }
    __syncthreads();

    // ---------------- GEMM4: o = h @ fW3^T ; symplectic swap -> out ----------------
    {
        const int mstrip = w >> 1, nf4 = w & 1;
        const uint2* wf3 = (const uint2*)(smx + O_WF);
        float o[4] = {0.0f, 0.0f, 0.0f, 0.0f};
#pragma unroll
        for (int kk = 0; kk < 16; ++kk) {
            uint4 A = sa4[(mstrip * 16 + kk) * 32 + lane];
            uint2 B = wf3[(kk * 2 + nf4) * 32 + lane];
            mma16816(o, A.x, A.y, A.z, A.w, B.x, B.y);
        }
        const int j0 = nf4 * 8 + 2 * fc;
        const int dst = (j0 + 8) & 15;
        const float sgn = (j0 < 8) ? -1.0f : 1.0f;
        const float b0 = smF[O_FB3 / 4 + j0], b1 = smF[O_FB3 / 4 + j0 + 1];
        const long rlo = n0 + mstrip * 16 + fr;
        *(float2*)(out + rlo * 16 + dst)       = make_float2(sgn * (o[0] + b0), sgn * (o[1] + b1));
        *(float2*)(out + (rlo + 8) * 16 + dst) = make_float2(sgn * (o[2] + b0), sgn * (o[3] + b1));
    }
}

extern "C" void kernel_launch(void* const* d_in, const int* in_sizes, int n_in,
                              void* d_out, int out_size)
{
    // metadata order: t, z, hW1, hb1, hW2, hb2, fW1, fb1, fW2, fb2, fW3, fb3
    const float* z   = (const float*)d_in[1];
    const float* hW1 = (const float*)d_in[2];
    const float* hb1 = (const float*)d_in[3];
    const float* hW2 = (const float*)d_in[4];
    const float* hb2 = (const float*)d_in[5];
    const float* fW1 = (const float*)d_in[6];
    const float* fb1 = (const float*)d_in[7];
    const float* fW2 = (const float*)d_in[8];
    const float* fb2 = (const float*)d_in[9];
    const float* fW3 = (const float*)d_in[10];
    const float* fb3 = (const float*)d_in[11];
    float* out = (float*)d_out;

    const int n = in_sizes[1] / 16;          // 131072 rows
    const int grid = n / BM;                 // 1024 CTAs

    prepack<<<132, NT>>>(hW2, fW2, fW3);

    cudaFuncSetAttribute(flexhnn_f16,
                         cudaFuncAttributeMaxDynamicSharedMemorySize, SMEMB);
    flexhnn_f16<<<grid, NT, SMEMB>>>(z, hW1, hb1, hb2, fW1, fb1, fb2, fb3, out);
}